// round 11
// baseline (speedup 1.0000x reference)
#include <cuda_runtime.h>
#include <cuda_bf16.h>
#include <cstdint>

// ---------------------------------------------------------------- constants
#define HW    16384
#define C     256
#define NFG   4096
#define NBG   12288
#define TOPK  20
#define MT    128
#define NT    128
#define FG_TILES 32
#define NTILES   128
#define CHUNK_K  64
#define NCHUNKS  (NTILES * 4)         // 512

#define THREADS 256
#define STAGES  3

// key(-inf) for the order-preserving float->uint encoding below
#define THR_NEG_INF 0x007FFFFFu

// A fragment-packed: [ks(16)][rowgrp(8)][lane(32)][4 x b32] = 64 KB
#define AF_U32   (16 * 8 * 32 * 4)
// B chunk: 128 rows x 64 k bf16, row stride 80 halves (160 B, conflict-free)
#define BPADH    80
#define B_HALFS  (128 * BPADH)        // 20 KB / stage
#define MG_FLOATS (THREADS * TOPK)    // 20 KB
#define SMEM_BYTES (AF_U32 * 4 + STAGES * B_HALFS * 2 + MG_FLOATS * 4 + 512)

// normalized bf16 features
__device__ __nv_bfloat16 g_sN[HW * C];     // row-major [pixel][k] (A path)
__device__ __nv_bfloat16 g_fgN[NFG * C];   // k-permuted within 16-groups (B path)
__device__ __nv_bfloat16 g_bgN[NBG * C];

// ---------------------------------------------------------------- helpers
__device__ __forceinline__ uint32_t smem_u32(const void* p) {
    uint32_t a;
    asm("{ .reg .u64 t; cvta.to.shared.u64 t, %1; cvt.u32.u64 %0, t; }"
        : "=r"(a) : "l"(p));
    return a;
}
__device__ __forceinline__ void cp_async16(uint32_t dst, const void* src) {
    asm volatile("cp.async.cg.shared.global [%0], [%1], 16;" :: "r"(dst), "l"(src));
}
__device__ __forceinline__ void cp_commit() {
    asm volatile("cp.async.commit_group;" ::: "memory");
}
__device__ __forceinline__ void cp_wait1() {
    asm volatile("cp.async.wait_group 1;" ::: "memory");
}
__device__ __forceinline__ void mma_bf16(float* d, const uint32_t* a,
                                         uint32_t b0, uint32_t b1) {
    asm volatile(
        "mma.sync.aligned.m16n8k16.row.col.f32.bf16.bf16.f32 "
        "{%0,%1,%2,%3}, {%4,%5,%6,%7}, {%8,%9}, {%0,%1,%2,%3};"
        : "+f"(d[0]), "+f"(d[1]), "+f"(d[2]), "+f"(d[3])
        : "r"(a[0]), "r"(a[1]), "r"(a[2]), "r"(a[3]), "r"(b0), "r"(b1));
}
// B k-permutation within 16-group
__device__ __forceinline__ int kperm16(int k) {
    return (k & ~15) | (((k & 7) >> 1) << 2) | (((k >> 3) & 1) << 1) | (k & 1);
}
// sorted-descending top list; no-op when v <= tl[TOPK-1]
__device__ __forceinline__ void topk_insert(float (&tl)[TOPK], float v) {
#pragma unroll
    for (int q = TOPK - 1; q >= 1; q--)
        tl[q] = (v > tl[q - 1]) ? tl[q - 1] : fmaxf(tl[q], v);
    tl[0] = fmaxf(tl[0], v);
}
// order-preserving float<->uint key (monotone for all non-NaN floats)
__device__ __forceinline__ uint32_t fkey(float f) {
    uint32_t b = __float_as_uint(f);
    return (b & 0x80000000u) ? ~b : (b | 0x80000000u);
}
__device__ __forceinline__ float funkey(uint32_t k) {
    return __uint_as_float((k & 0x80000000u) ? (k ^ 0x80000000u) : ~k);
}

// ---------------------------------------------------------------- normalize
__global__ void norm_s_kernel(const float* __restrict__ s) {
    int p = blockIdx.x * blockDim.x + threadIdx.x;
    float ss = 0.f;
#pragma unroll 8
    for (int c = 0; c < C; c++) { float v = s[c * HW + p]; ss += v * v; }
    float sc = 1.f / fmaxf(sqrtf(ss), 1e-12f);
#pragma unroll 8
    for (int c = 0; c < C; c++)
        g_sN[p * C + c] = __float2bfloat16_rn(s[c * HW + p] * sc);
}

__global__ void norm_rows_kernel(const float* __restrict__ x, int R, int isBg) {
    __nv_bfloat16* __restrict__ y = isBg ? g_bgN : g_fgN;
    int gwarp = (blockIdx.x * blockDim.x + threadIdx.x) >> 5;
    int lane  = threadIdx.x & 31;
    int nwarp = (gridDim.x * blockDim.x) >> 5;
    for (int r = gwarp; r < R; r += nwarp) {
        const float* xr = x + (size_t)r * C;
        float v[8]; float ss = 0.f;
#pragma unroll
        for (int j = 0; j < 8; j++) { v[j] = xr[lane + 32 * j]; ss += v[j] * v[j]; }
#pragma unroll
        for (int o = 16; o; o >>= 1) ss += __shfl_xor_sync(0xffffffffu, ss, o);
        float sc = 1.f / fmaxf(sqrtf(ss), 1e-12f);
        __nv_bfloat16* yr = y + (size_t)r * C;
#pragma unroll
        for (int j = 0; j < 8; j++) {
            int k = lane + 32 * j;
            yr[kperm16(k)] = __float2bfloat16_rn(v[j] * sc);
        }
    }
}

// ---------------------------------------------------------------- main kernel
// 8 warps: mwarp = wid>>1 (rows mwarp*32), nwarp = wid&1 (cols nwarp*64).
// Warp tile 32x64 via m16n8k16 bf16. Per-row union thresholds in smem.
__global__ __launch_bounds__(THREADS, 1) void gemm_topk(float* __restrict__ out) {
    extern __shared__ char smc[];
    uint32_t*       AfU = (uint32_t*)smc;
    __nv_bfloat16*  Bsh = (__nv_bfloat16*)(smc + AF_U32 * 4);
    float*          Mg  = (float*)(smc + AF_U32 * 4 + STAGES * B_HALFS * 2);
    uint32_t*       ThrU = (uint32_t*)(Mg + MG_FLOATS);   // [128] per-row keys

    const int tid   = threadIdx.x;
    const int lane  = tid & 31;
    const int wid   = tid >> 5;
    const int mwarp = wid >> 1;
    const int nwarp = wid & 1;
    const int g4    = lane >> 2;
    const int t4    = lane & 3;
    const int mb    = blockIdx.x;

    if (tid < MT) ThrU[tid] = THR_NEG_INF;     // decodes to -inf

    // ---- stage A into m16n8k16 fragment layout (once) ----
    {
        const uint4* Ag = (const uint4*)(g_sN + (size_t)mb * MT * C);
#pragma unroll
        for (int j = 0; j < 16; j++) {
            int idx = tid + j * THREADS;
            int r   = idx >> 5;
            int j8  = idx & 31;
            uint4 v = Ag[idx];
            int ks     = j8 >> 1;
            int khalf  = j8 & 1;
            int rowgrp = r >> 4, g4r = r & 7, rowhalf = (r >> 3) & 1;
            int reg  = rowhalf + 2 * khalf;
            uint32_t* base = AfU + ((ks * 8 + rowgrp) * 32) * 4 + reg;
            uint32_t w[4] = { v.x, v.y, v.z, v.w };
#pragma unroll
            for (int p = 0; p < 4; p++)
                base[(g4r * 4 + p) * 4] = w[p];
        }
    }

    // ---- B prefetch into stage buffer (chunk = 64 k) ----
    uint32_t bsa = smem_u32(Bsh);
    auto issueB = [&](int ci) {
        if (ci < NCHUNKS) {
            int t  = ci >> 2, kc = ci & 3;
            const __nv_bfloat16* src =
                (t < FG_TILES ? g_fgN + (size_t)t * NT * C
                              : g_bgN + (size_t)(t - FG_TILES) * NT * C)
                + kc * CHUNK_K;
            uint32_t sb = bsa + (uint32_t)((ci % STAGES) * B_HALFS) * 2u;
#pragma unroll
            for (int j = 0; j < 4; j++) {
                int idx = tid + j * THREADS;
                int n   = idx >> 3;
                int jj  = idx & 7;
                cp_async16(sb + (uint32_t)(n * BPADH * 2 + jj * 16),
                           (const char*)src + (size_t)n * C * 2 + jj * 16);
            }
        }
        cp_commit();
    };
    issueB(0);
    issueB(1);

    // ---- top-K state: 4 row-streams, sorted desc in registers ----
    float top[4][TOPK];
#pragma unroll
    for (int p = 0; p < 4; p++)
#pragma unroll
        for (int q = 0; q < TOPK; q++) top[p][q] = -1e30f;

    float acc[2][8][4];
#pragma unroll
    for (int mt = 0; mt < 2; mt++)
#pragma unroll
        for (int nt = 0; nt < 8; nt++)
#pragma unroll
            for (int c = 0; c < 4; c++) acc[mt][nt][c] = 0.f;

#pragma unroll 1
    for (int ci = 0; ci < NCHUNKS; ci++) {
        cp_wait1();
        __syncthreads();
        issueB(ci + STAGES - 1);
        const __nv_bfloat16* Bb = Bsh + (ci % STAGES) * B_HALFS;

#pragma unroll
        for (int s = 0; s < 4; s++) {
            int ks = (ci & 3) * 4 + s;
            uint32_t a[2][4];
#pragma unroll
            for (int mt = 0; mt < 2; mt++) {
                uint4 v = *(const uint4*)&AfU[((ks * 8 + (mwarp * 2 + mt)) * 32 + lane) * 4];
                a[mt][0] = v.x; a[mt][1] = v.y; a[mt][2] = v.z; a[mt][3] = v.w;
            }
#pragma unroll
            for (int nt = 0; nt < 8; nt++) {
                int cg = nwarp * 8 + nt;
                uint2 b = *(const uint2*)(Bb + (cg * 8 + g4) * BPADH + s * 16 + t4 * 4);
                mma_bf16(acc[0][nt], a[0], b.x, b.y);
                mma_bf16(acc[1][nt], a[1], b.x, b.y);
            }
        }

        if ((ci & 3) == 3) {                   // tile finished
            // ---- top-K update, gated by shared per-row union threshold ----
#pragma unroll
            for (int p = 0; p < 4; p++) {
                const int mt = p >> 1, h = p & 1;
                const int row = mwarp * 32 + mt * 16 + h * 8 + g4;
                float thr = funkey(ThrU[row]);
                float mx = -1e30f;
#pragma unroll
                for (int nt = 0; nt < 8; nt++) {
                    mx = fmaxf(mx, acc[mt][nt][2 * h]);
                    mx = fmaxf(mx, acc[mt][nt][2 * h + 1]);
                }
                if (mx > thr) {                // divergence-safe: no sync ops inside
#pragma unroll
                    for (int nt = 0; nt < 8; nt++) {
#pragma unroll
                        for (int cc = 0; cc < 2; cc++) {
                            float v = acc[mt][nt][2 * h + cc];
                            if (v > thr) topk_insert(top[p], v);
                        }
                    }
                }
                // union bound of this row's 4 sub-list 20ths — UNCONDITIONAL
                // shuffles (all 32 lanes participate; partners are t4 xor 1,2)
                float t19 = top[p][TOPK - 1];
                t19 = fmaxf(t19, __shfl_xor_sync(0xffffffffu, t19, 1));
                t19 = fmaxf(t19, __shfl_xor_sync(0xffffffffu, t19, 2));
                if (t4 == 0 && t19 > thr)      // publish only on improvement
                    atomicMax(&ThrU[row], fkey(t19));
            }
#pragma unroll
            for (int mt = 0; mt < 2; mt++)
#pragma unroll
                for (int nt = 0; nt < 8; nt++)
#pragma unroll
                    for (int c = 0; c < 4; c++) acc[mt][nt][c] = 0.f;

            int t = ci >> 2;
            if (t == FG_TILES - 1 || t == NTILES - 1) {
                float* obase = out + (t == FG_TILES - 1 ? 0 : HW) + mb * MT;
#pragma unroll
                for (int p = 0; p < 4; p++) {
                    const int mt = p >> 1, h = p & 1;
#pragma unroll
                    for (int q = 0; q < TOPK; q++) Mg[tid * TOPK + q] = top[p][q];
                    __syncthreads();
                    if (tid < 32) {
                        int mw = tid >> 3, rg = tid & 7;
                        int row = mw * 32 + mt * 16 + h * 8 + rg;
                        float best[TOPK];
#pragma unroll
                        for (int q = 0; q < TOPK; q++) best[q] = -1e30f;
                        for (int nw = 0; nw < 2; nw++) {
                            for (int l = 0; l < 4; l++) {
                                int slot = (mw * 2 + nw) * 32 + rg * 4 + l;
                                for (int q = 0; q < TOPK; q++) {
                                    float v = Mg[slot * TOPK + q];
                                    if (v > best[TOPK - 1]) topk_insert(best, v);
                                }
                            }
                        }
                        float ssum = 0.f;
#pragma unroll
                        for (int q = 0; q < TOPK; q++) ssum += best[q];
                        obase[row] = ssum * (1.0f / TOPK);
                    }
                    __syncthreads();
#pragma unroll
                    for (int q = 0; q < TOPK; q++) top[p][q] = -1e30f;
                }
                if (tid < MT) ThrU[tid] = THR_NEG_INF;   // reset for bg stream
                __syncthreads();
            }
        }
    }
}

// ---------------------------------------------------------------- launch
extern "C" void kernel_launch(void* const* d_in, const int* in_sizes, int n_in,
                              void* d_out, int out_size) {
    const float* s  = (const float*)d_in[0];
    const float* fg = (const float*)d_in[1];
    const float* bg = (const float*)d_in[2];
    float* out = (float*)d_out;

    cudaFuncSetAttribute(gemm_topk,
                         cudaFuncAttributeMaxDynamicSharedMemorySize, SMEM_BYTES);

    norm_s_kernel<<<HW / 128, 128>>>(s);
    norm_rows_kernel<<<128, 256>>>(fg, NFG, 0);
    norm_rows_kernel<<<128, 256>>>(bg, NBG, 1);
    gemm_topk<<<HW / MT, THREADS, SMEM_BYTES>>>(out);
}

// round 13
// speedup vs baseline: 1.2676x; 1.2676x over previous
#include <cuda_runtime.h>
#include <cuda_bf16.h>
#include <cstdint>

// ---------------------------------------------------------------- constants
#define HW    16384
#define C     256
#define NFG   4096
#define NBG   12288
#define TOPK  20
#define MT    128
#define NT    128
#define FG_TILES 32
#define NTILES   128
#define CHUNK_K  64
#define NCHUNKS  (NTILES * 4)         // 512

#define THREADS 512                   // 16 warps: 4 mwarp x 4 nwarp
#define STAGES  3

// key(-inf) for the order-preserving float->uint encoding below
#define THR_NEG_INF 0x007FFFFFu

// A fragment-packed: [ks(16)][rowgrp(8)][lane(32)][4 x b32] = 64 KB
#define AF_U32   (16 * 8 * 32 * 4)
// B chunk: 128 rows x 64 k bf16, row stride 80 halves (conflict-free)
#define BPADH    80
#define B_HALFS  (128 * BPADH)        // 20 KB / stage
// per-warp transpose buffer: 32 rows x 36 floats (144 B row: 16B-aligned,
// conflict-free for both the float4 stores and loads), 16 warps
#define W_STRIDE 36
#define W_FLOATS (16 * 32 * W_STRIDE) // 18432 floats (also reused as merge buf)
#define SMEM_BYTES (AF_U32 * 4 + STAGES * B_HALFS * 2 + W_FLOATS * 4 + 512)

// normalized bf16 features
__device__ __nv_bfloat16 g_sN[HW * C];     // row-major [pixel][k] (A path)
__device__ __nv_bfloat16 g_fgN[NFG * C];   // k-permuted within 16-groups (B path)
__device__ __nv_bfloat16 g_bgN[NBG * C];

// ---------------------------------------------------------------- helpers
__device__ __forceinline__ uint32_t smem_u32(const void* p) {
    uint32_t a;
    asm("{ .reg .u64 t; cvta.to.shared.u64 t, %1; cvt.u32.u64 %0, t; }"
        : "=r"(a) : "l"(p));
    return a;
}
__device__ __forceinline__ void cp_async16(uint32_t dst, const void* src) {
    asm volatile("cp.async.cg.shared.global [%0], [%1], 16;" :: "r"(dst), "l"(src));
}
__device__ __forceinline__ void cp_commit() {
    asm volatile("cp.async.commit_group;" ::: "memory");
}
__device__ __forceinline__ void cp_wait1() {
    asm volatile("cp.async.wait_group 1;" ::: "memory");
}
__device__ __forceinline__ void mma_bf16(float* d, const uint32_t* a,
                                         uint32_t b0, uint32_t b1) {
    asm volatile(
        "mma.sync.aligned.m16n8k16.row.col.f32.bf16.bf16.f32 "
        "{%0,%1,%2,%3}, {%4,%5,%6,%7}, {%8,%9}, {%0,%1,%2,%3};"
        : "+f"(d[0]), "+f"(d[1]), "+f"(d[2]), "+f"(d[3])
        : "r"(a[0]), "r"(a[1]), "r"(a[2]), "r"(a[3]), "r"(b0), "r"(b1));
}
// B k-permutation within 16-group
__device__ __forceinline__ int kperm16(int k) {
    return (k & ~15) | (((k & 7) >> 1) << 2) | (((k >> 3) & 1) << 1) | (k & 1);
}
// sorted-descending top list; no-op when v <= tl[TOPK-1]
__device__ __forceinline__ void topk_insert(float (&tl)[TOPK], float v) {
#pragma unroll
    for (int q = TOPK - 1; q >= 1; q--)
        tl[q] = (v > tl[q - 1]) ? tl[q - 1] : fmaxf(tl[q], v);
    tl[0] = fmaxf(tl[0], v);
}
// order-preserving float<->uint key (monotone for all non-NaN floats)
__device__ __forceinline__ uint32_t fkey(float f) {
    uint32_t b = __float_as_uint(f);
    return (b & 0x80000000u) ? ~b : (b | 0x80000000u);
}
__device__ __forceinline__ float funkey(uint32_t k) {
    return __uint_as_float((k & 0x80000000u) ? (k ^ 0x80000000u) : ~k);
}

// ---------------------------------------------------------------- normalize
__global__ void norm_s_kernel(const float* __restrict__ s) {
    int p = blockIdx.x * blockDim.x + threadIdx.x;
    float ss = 0.f;
#pragma unroll 8
    for (int c = 0; c < C; c++) { float v = s[c * HW + p]; ss += v * v; }
    float sc = 1.f / fmaxf(sqrtf(ss), 1e-12f);
#pragma unroll 8
    for (int c = 0; c < C; c++)
        g_sN[p * C + c] = __float2bfloat16_rn(s[c * HW + p] * sc);
}

__global__ void norm_rows_kernel(const float* __restrict__ x, int R, int isBg) {
    __nv_bfloat16* __restrict__ y = isBg ? g_bgN : g_fgN;
    int gwarp = (blockIdx.x * blockDim.x + threadIdx.x) >> 5;
    int lane  = threadIdx.x & 31;
    int nwarp = (gridDim.x * blockDim.x) >> 5;
    for (int r = gwarp; r < R; r += nwarp) {
        const float* xr = x + (size_t)r * C;
        float v[8]; float ss = 0.f;
#pragma unroll
        for (int j = 0; j < 8; j++) { v[j] = xr[lane + 32 * j]; ss += v[j] * v[j]; }
#pragma unroll
        for (int o = 16; o; o >>= 1) ss += __shfl_xor_sync(0xffffffffu, ss, o);
        float sc = 1.f / fmaxf(sqrtf(ss), 1e-12f);
        __nv_bfloat16* yr = y + (size_t)r * C;
#pragma unroll
        for (int j = 0; j < 8; j++) {
            int k = lane + 32 * j;
            yr[kperm16(k)] = __float2bfloat16_rn(v[j] * sc);
        }
    }
}

// ---------------------------------------------------------------- main kernel
// 16 warps: mwarp = wid>>2 (rows mwarp*32), nwarp = wid&3 (cols nwarp*32).
// Warp tile 32x32 via m16n8k16 bf16 (mt in {0,1}, nt in {0..3}).
// After each tile: per-warp smem transpose so each lane owns ONE row's 32
// values; single register top-20 per lane; per-row union thresholds in smem.
__global__ __launch_bounds__(THREADS, 1) void gemm_topk(float* __restrict__ out) {
    extern __shared__ char smc[];
    uint32_t*       AfU  = (uint32_t*)smc;
    __nv_bfloat16*  Bsh  = (__nv_bfloat16*)(smc + AF_U32 * 4);
    float*          Wbuf = (float*)(smc + AF_U32 * 4 + STAGES * B_HALFS * 2);
    uint32_t*       ThrU = (uint32_t*)(Wbuf + W_FLOATS);   // [128] row keys

    const int tid   = threadIdx.x;
    const int lane  = tid & 31;
    const int wid   = tid >> 5;
    const int mwarp = wid >> 2;
    const int nwarp = wid & 3;
    const int g4    = lane >> 2;
    const int t4    = lane & 3;
    const int mb    = blockIdx.x;
    const int myrow = mwarp * 32 + lane;       // row this lane owns post-transpose

    if (tid < MT) ThrU[tid] = THR_NEG_INF;

    // ---- stage A into m16n8k16 fragment layout (once) ----
    {
        const uint4* Ag = (const uint4*)(g_sN + (size_t)mb * MT * C);
#pragma unroll
        for (int j = 0; j < 8; j++) {
            int idx = tid + j * THREADS;       // 4096 uint4
            int r   = idx >> 5;
            int j8  = idx & 31;
            uint4 v = Ag[idx];
            int ks     = j8 >> 1;
            int khalf  = j8 & 1;
            int rowgrp = r >> 4, g4r = r & 7, rowhalf = (r >> 3) & 1;
            int reg  = rowhalf + 2 * khalf;
            uint32_t* base = AfU + ((ks * 8 + rowgrp) * 32) * 4 + reg;
            uint32_t w[4] = { v.x, v.y, v.z, v.w };
#pragma unroll
            for (int p = 0; p < 4; p++)
                base[(g4r * 4 + p) * 4] = w[p];
        }
    }

    // ---- B prefetch into stage buffer (chunk = 64 k) ----
    uint32_t bsa = smem_u32(Bsh);
    auto issueB = [&](int ci) {
        if (ci < NCHUNKS) {
            int t  = ci >> 2, kc = ci & 3;
            const __nv_bfloat16* src =
                (t < FG_TILES ? g_fgN + (size_t)t * NT * C
                              : g_bgN + (size_t)(t - FG_TILES) * NT * C)
                + kc * CHUNK_K;
            uint32_t sb = bsa + (uint32_t)((ci % STAGES) * B_HALFS) * 2u;
#pragma unroll
            for (int j = 0; j < 2; j++) {
                int idx = tid + j * THREADS;   // 1024 x 16B
                int n   = idx >> 3;
                int jj  = idx & 7;
                cp_async16(sb + (uint32_t)(n * BPADH * 2 + jj * 16),
                           (const char*)src + (size_t)n * C * 2 + jj * 16);
            }
        }
        cp_commit();
    };
    issueB(0);
    issueB(1);

    // ---- top-K state: ONE row-stream per lane, sorted desc in registers ----
    float top[TOPK];
#pragma unroll
    for (int q = 0; q < TOPK; q++) top[q] = -1e30f;

    float acc[2][4][4];
#pragma unroll
    for (int mt = 0; mt < 2; mt++)
#pragma unroll
        for (int nt = 0; nt < 4; nt++)
#pragma unroll
            for (int c = 0; c < 4; c++) acc[mt][nt][c] = 0.f;

    float* Wp = Wbuf + wid * 32 * W_STRIDE;    // this warp's transpose buffer

#pragma unroll 1
    for (int ci = 0; ci < NCHUNKS; ci++) {
        cp_wait1();
        __syncthreads();
        issueB(ci + STAGES - 1);
        const __nv_bfloat16* Bb = Bsh + (ci % STAGES) * B_HALFS;

#pragma unroll
        for (int s = 0; s < 4; s++) {
            int ks = (ci & 3) * 4 + s;
            uint32_t a[2][4];
#pragma unroll
            for (int mt = 0; mt < 2; mt++) {
                uint4 v = *(const uint4*)&AfU[((ks * 8 + (mwarp * 2 + mt)) * 32 + lane) * 4];
                a[mt][0] = v.x; a[mt][1] = v.y; a[mt][2] = v.z; a[mt][3] = v.w;
            }
#pragma unroll
            for (int nt = 0; nt < 4; nt++) {
                int cg = nwarp * 4 + nt;
                uint2 b = *(const uint2*)(Bb + (cg * 8 + g4) * BPADH + s * 16 + t4 * 4);
                mma_bf16(acc[0][nt], a[0], b.x, b.y);
                mma_bf16(acc[1][nt], a[1], b.x, b.y);
            }
        }

        if ((ci & 3) == 3) {                   // tile finished
            // ---- warp-local transpose: lane -> one full row slice ----
            __syncwarp();                      // WAR vs previous tile's reads
#pragma unroll
            for (int mt = 0; mt < 2; mt++) {
#pragma unroll
                for (int h = 0; h < 2; h++) {
                    int r = mt * 16 + h * 8 + g4;
                    float* dst = Wp + r * W_STRIDE + t4 * 8;
                    float4 v0 = { acc[mt][0][2*h], acc[mt][0][2*h+1],
                                  acc[mt][1][2*h], acc[mt][1][2*h+1] };
                    float4 v1 = { acc[mt][2][2*h], acc[mt][2][2*h+1],
                                  acc[mt][3][2*h], acc[mt][3][2*h+1] };
                    *(float4*)dst       = v0;
                    *(float4*)(dst + 4) = v1;
                }
            }
            __syncwarp();
            float v[32];
#pragma unroll
            for (int k = 0; k < 8; k++) {
                float4 r4 = *(const float4*)&Wp[lane * W_STRIDE + k * 4];
                v[4*k] = r4.x; v[4*k+1] = r4.y; v[4*k+2] = r4.z; v[4*k+3] = r4.w;
            }

            // ---- top-K update for my row, gated by union threshold ----
            float thr = fmaxf(top[TOPK - 1], funkey(ThrU[myrow]));
            float mx = v[0];
#pragma unroll
            for (int i = 1; i < 32; i++) mx = fmaxf(mx, v[i]);
            if (mx > thr) {
#pragma unroll
                for (int i = 0; i < 32; i++)
                    if (v[i] > thr) topk_insert(top, v[i]);
                float t19 = top[TOPK - 1];
                if (t19 > thr) atomicMax(&ThrU[myrow], fkey(t19));
            }

#pragma unroll
            for (int mt = 0; mt < 2; mt++)
#pragma unroll
                for (int nt = 0; nt < 4; nt++)
#pragma unroll
                    for (int c = 0; c < 4; c++) acc[mt][nt][c] = 0.f;

            int t = ci >> 2;
            if (t == FG_TILES - 1 || t == NTILES - 1) {
                // ---- merge 4 nwarp sub-lists per row, write output ----
                float* obase = out + (t == FG_TILES - 1 ? 0 : HW) + mb * MT;
                __syncthreads();               // everyone done with Wbuf
                float* Mg = Wbuf;              // reuse as merge buffer
#pragma unroll
                for (int q = 0; q < TOPK; q++) Mg[tid * TOPK + q] = top[q];
                __syncthreads();
                if (tid < MT) {
                    int mw = tid >> 5, ln = tid & 31;
                    float best[TOPK];
#pragma unroll
                    for (int q = 0; q < TOPK; q++) best[q] = -1e30f;
                    for (int nw = 0; nw < 4; nw++) {
                        int slot = (mw * 4 + nw) * 32 + ln;
                        for (int q = 0; q < TOPK; q++) {
                            float vv = Mg[slot * TOPK + q];
                            if (vv > best[TOPK - 1]) topk_insert(best, vv);
                            else break;        // source list sorted desc
                        }
                    }
                    float ssum = 0.f;
#pragma unroll
                    for (int q = 0; q < TOPK; q++) ssum += best[q];
                    obase[tid] = ssum * (1.0f / TOPK);
                }
#pragma unroll
                for (int q = 0; q < TOPK; q++) top[q] = -1e30f;
                if (tid < MT) ThrU[tid] = THR_NEG_INF;
                __syncthreads();
            }
        }
    }
}

// ---------------------------------------------------------------- launch
extern "C" void kernel_launch(void* const* d_in, const int* in_sizes, int n_in,
                              void* d_out, int out_size) {
    const float* s  = (const float*)d_in[0];
    const float* fg = (const float*)d_in[1];
    const float* bg = (const float*)d_in[2];
    float* out = (float*)d_out;

    cudaFuncSetAttribute(gemm_topk,
                         cudaFuncAttributeMaxDynamicSharedMemorySize, SMEM_BYTES);

    norm_s_kernel<<<HW / 128, 128>>>(s);
    norm_rows_kernel<<<128, 256>>>(fg, NFG, 0);
    norm_rows_kernel<<<128, 256>>>(bg, NBG, 1);
    gemm_topk<<<HW / MT, THREADS, SMEM_BYTES>>>(out);
}